// round 15
// baseline (speedup 1.0000x reference)
#include <cuda_runtime.h>
#include <math.h>
#include <stdint.h>

#define D_MODEL 1024
#define NHEAD   16
#define D_HEAD  64
#define B_      2
#define S_      2048
#define M_ROWS  (B_*S_)              // 4096
#define AELEM   (M_ROWS * D_MODEL)   // 4M
#define WELEM   (D_MODEL * D_MODEL)  // 1M

// ---------------- scratch (allocation-free) ----------------
__device__ float g_ta[3 * AELEM];   // tf32 inputs q,k,v; seg0 reused for attn output
__device__ float g_tw[4 * WELEM];   // tf32 weights wq,wk,wv,wo
__device__ float g_v [AELEM];       // V projection (fp32)
__device__ float g_qt[AELEM];       // scaled Q (log2e folded), tf32
__device__ float g_kt[AELEM];       // K, tf32
__device__ float g_vt[AELEM];       // V^T per head [bh][64][2048], tf32
__device__ uint32_t g_mbits[B_ * S_ * (S_/32)];

// ---------------- helpers ----------------
__device__ __forceinline__ uint32_t smem_u32(const void* p) {
    uint32_t a;
    asm("{ .reg .u64 t; cvta.to.shared.u64 t, %1; cvt.u32.u64 %0, t; }" : "=r"(a) : "l"(p));
    return a;
}
#define CP16(dst, src) \
    asm volatile("cp.async.cg.shared.global [%0], [%1], 16;" :: "r"(dst), "l"(src))
#define CP_COMMIT() asm volatile("cp.async.commit_group;" ::: "memory")
#define CP_WAIT0()  asm volatile("cp.async.wait_group 0;" ::: "memory")
#define LDSM4(d, a) \
    asm volatile("ldmatrix.sync.aligned.m8n8.x4.shared.b16 {%0,%1,%2,%3}, [%4];" \
        : "=r"((d)[0]), "=r"((d)[1]), "=r"((d)[2]), "=r"((d)[3]) : "r"(a))
#define MMA1688(c, a, b0, b1) \
    asm volatile("mma.sync.aligned.m16n8k8.row.col.f32.tf32.tf32.f32 " \
        "{%0,%1,%2,%3},{%4,%5,%6,%7},{%8,%9},{%0,%1,%2,%3};" \
        : "+f"((c)[0]), "+f"((c)[1]), "+f"((c)[2]), "+f"((c)[3]) \
        : "r"((a)[0]), "r"((a)[1]), "r"((a)[2]), "r"((a)[3]), "r"(b0), "r"(b1))

__device__ __forceinline__ uint32_t tf32r(float x) {
    uint32_t r;
    asm("cvt.rna.tf32.f32 %0, %1;" : "=r"(r) : "f"(x));
    return r;
}
__device__ __forceinline__ float tf32f(float x) { uint32_t r = tf32r(x); return __uint_as_float(r); }
__device__ __forceinline__ float ex2(float x) {
    float y;
    asm("ex2.approx.ftz.f32 %0, %1;" : "=f"(y) : "f"(x));
    return y;
}
#define QSCALE 0.1803368801111243f   /* 0.125 * log2(e) */

// ---------------- prep: tf32 rounding (7 tensors) + mask bitpack, one launch ----------------
__global__ __launch_bounds__(256) void prep_all(
    const float* __restrict__ q, const float* __restrict__ k, const float* __restrict__ v,
    const float* __restrict__ wq, const float* __restrict__ wk,
    const float* __restrict__ wv, const float* __restrict__ wo,
    const int* __restrict__ mask)
{
    const int y = blockIdx.y;
    if (y == 7) {
        int gw = blockIdx.x * 8 + (threadIdx.x >> 5);
        int lane = threadIdx.x & 31;
        #pragma unroll
        for (int i = 0; i < 8; i++) {
            int w = gw * 8 + i;
            int m = mask[((size_t)(w >> 6) << 11) + ((w & 63) << 5) + lane];
            uint32_t word = __ballot_sync(0xffffffffu, m != 0);
            if (lane == 0) g_mbits[w] = word;
        }
        return;
    }
    const float* src; float* dst; int n4;
    if (y < 3) { src = (y==0)?q:(y==1)?k:v; dst = g_ta + (size_t)y * AELEM; n4 = AELEM/4; }
    else { int w = y-3; src = (w==0)?wq:(w==1)?wk:(w==2)?wv:wo; dst = g_tw + (size_t)w*WELEM; n4 = WELEM/4; }
    int i = blockIdx.x * blockDim.x + threadIdx.x;
    if (i >= n4) return;
    float4 x = ((const float4*)src)[i];
    x.x = tf32f(x.x); x.y = tf32f(x.y); x.z = tf32f(x.z); x.w = tf32f(x.w);
    ((float4*)dst)[i] = x;
}

// ---------------- V transpose + round ----------------
__global__ __launch_bounds__(256) void vtrans(void)
{
    __shared__ float t[32][33];
    const int bh = blockIdx.z, kt = blockIdx.x, dt = blockIdx.y;
    const int tx = threadIdx.x, ty = threadIdx.y;
    const size_t ho = (size_t)bh * S_ * D_HEAD;
    #pragma unroll
    for (int i = 0; i < 4; i++) {
        int key = kt * 32 + ty + i * 8;
        t[ty + i * 8][tx] = g_v[ho + (size_t)key * D_HEAD + dt * 32 + tx];
    }
    __syncthreads();
    #pragma unroll
    for (int i = 0; i < 4; i++) {
        int d   = dt * 32 + ty + i * 8;
        int key = kt * 32 + tx;
        g_vt[ho + (size_t)d * S_ + key] = tf32f(t[tx][ty + i * 8]);
    }
}

// ---------------- tf32 GEMM mainloop (R14: 2-stage, pipelined frags) ----------------
#define GS_STRIDE 144
#define GS_TILE   (128 * GS_STRIDE)
#define GS_STAGE  (2 * GS_TILE)
#define GSMEM     (2 * GS_STAGE)
#define NKB       (D_MODEL / 32)

__device__ __forceinline__ void gemm_body(
    const float* __restrict__ A, const float* __restrict__ W,
    uint32_t sbase, int m0, int n0, int tid, float acc[2][8][4])
{
    const int wid  = tid >> 5, lane = tid & 31;
    const int wm   = wid & 3,  wn   = wid >> 2;
    const int lr   = lane & 7;
    const int ls8  = ((lane >> 3) & 1) << 3;
    const int lc16 = ((lane >> 4) & 1) << 4;

    auto load_stage = [&](int kb, int s) {
        const int k0 = kb * 32;
        const uint32_t stb = sbase + s * GS_STAGE;
        #pragma unroll
        for (int j = 0; j < 8; j++) {
            int c  = j * 256 + tid;
            int t  = c >> 10;
            int r  = (c >> 3) & 127;
            int cc = c & 7;
            uint32_t dst = stb + t * GS_TILE + r * GS_STRIDE + cc * 16;
            const float* src = (t ? W : A) + ((size_t)((t ? n0 : m0) + r) << 10) + k0 + cc * 4;
            CP16(dst, src);
        }
        CP_COMMIT();
    };

    uint32_t af[2][2][4], bf[2][4][4];
    const uint32_t rowAoff = (wm * 32 + lr + ls8) * GS_STRIDE;
    const uint32_t rowBoff = GS_TILE + (wn * 64 + lr + ls8) * GS_STRIDE;

    auto ld_frags = [&](uint32_t stb, int k8, int s) {
        const uint32_t colOff = k8 * 32 + lc16;
        #pragma unroll
        for (int mt = 0; mt < 2; mt++)
            LDSM4(af[s][mt], stb + rowAoff + mt * (16 * GS_STRIDE) + colOff);
        #pragma unroll
        for (int p = 0; p < 4; p++)
            LDSM4(bf[s][p], stb + rowBoff + p * (16 * GS_STRIDE) + colOff);
    };

    #pragma unroll
    for (int mt = 0; mt < 2; mt++)
        #pragma unroll
        for (int nt = 0; nt < 8; nt++)
            #pragma unroll
            for (int e = 0; e < 4; e++) acc[mt][nt][e] = 0.f;

    load_stage(0, 0);
    CP_WAIT0();
    __syncthreads();
    load_stage(1, 1);
    ld_frags(sbase, 0, 0);

    for (int kb = 0; kb < NKB; kb++) {
        const uint32_t stb = sbase + (kb & 1) * GS_STAGE;
        #pragma unroll
        for (int k8 = 0; k8 < 4; k8++) {
            const int s = k8 & 1;
            if (k8 < 3) {
                ld_frags(stb, k8 + 1, s ^ 1);
            } else if (kb + 1 < NKB) {
                CP_WAIT0();
                __syncthreads();
                if (kb + 2 < NKB) load_stage(kb + 2, kb & 1);
                ld_frags(sbase + ((kb + 1) & 1) * GS_STAGE, 0, s ^ 1);
            }
            #pragma unroll
            for (int mt = 0; mt < 2; mt++)
                #pragma unroll
                for (int nt = 0; nt < 8; nt++) {
                    const int p = nt >> 1, ss = nt & 1;
                    MMA1688(acc[mt][nt], af[s][mt], bf[s][p][ss], bf[s][p][ss + 2]);
                }
        }
    }
}

// ---------------- fused Q/K/V projections ----------------
__global__ __launch_bounds__(256, 2) void gemm_qkv(void)
{
    extern __shared__ char sm[];
    const uint32_t sbase = smem_u32(sm);
    const int tid = threadIdx.x;
    const int z   = blockIdx.z;
    const int m0  = blockIdx.y * 128, n0 = blockIdx.x * 128;

    const float* A = g_ta + (size_t)z * AELEM;
    const float* W = g_tw + (size_t)z * WELEM;

    float acc[2][8][4];
    gemm_body(A, W, sbase, m0, n0, tid, acc);

    const int wid = tid >> 5, lane = tid & 31;
    const int wm = wid & 3, wn = wid >> 2;
    const int erow = lane >> 2, ecol = (lane & 3) << 1;
    const float scale = (z == 0) ? QSCALE : 1.f;
    #pragma unroll
    for (int mt = 0; mt < 2; mt++)
        #pragma unroll
        for (int nt = 0; nt < 8; nt++) {
            int gr = m0 + wm * 32 + mt * 16 + erow;
            int gc = n0 + wn * 64 + nt * 8 + ecol;
            size_t o0 = (size_t)gr * D_MODEL + gc;
            size_t o1 = (size_t)(gr + 8) * D_MODEL + gc;
            if (z == 2) {
                *(float2*)&g_v[o0] = make_float2(acc[mt][nt][0], acc[mt][nt][1]);
                *(float2*)&g_v[o1] = make_float2(acc[mt][nt][2], acc[mt][nt][3]);
            } else {
                float* T = (z == 0) ? g_qt : g_kt;
                *(float2*)&T[o0] = make_float2(tf32f(acc[mt][nt][0] * scale),
                                               tf32f(acc[mt][nt][1] * scale));
                *(float2*)&T[o1] = make_float2(tf32f(acc[mt][nt][2] * scale),
                                               tf32f(acc[mt][nt][3] * scale));
            }
        }
}

// ---------------- O projection ----------------
__global__ __launch_bounds__(256, 2) void gemm_o(float* __restrict__ C)
{
    extern __shared__ char sm[];
    const uint32_t sbase = smem_u32(sm);
    const int tid = threadIdx.x;
    const int m0  = blockIdx.y * 128, n0 = blockIdx.x * 128;

    float acc[2][8][4];
    gemm_body(g_ta, g_tw + 3 * (size_t)WELEM, sbase, m0, n0, tid, acc);

    const int wid = tid >> 5, lane = tid & 31;
    const int wm = wid & 3, wn = wid >> 2;
    const int erow = lane >> 2, ecol = (lane & 3) << 1;
    #pragma unroll
    for (int mt = 0; mt < 2; mt++)
        #pragma unroll
        for (int nt = 0; nt < 8; nt++) {
            int gr = m0 + wm * 32 + mt * 16 + erow;
            int gc = n0 + wn * 64 + nt * 8 + ecol;
            *(float2*)&C[(size_t)gr * D_MODEL + gc] =
                make_float2(acc[mt][nt][0], acc[mt][nt][1]);
            *(float2*)&C[(size_t)(gr + 8) * D_MODEL + gc] =
                make_float2(acc[mt][nt][2], acc[mt][nt][3]);
        }
}

// ---------------- tf32 flash attention: 4 q-warps x m32, 2 key-halves ----------------
#define AQ_STRIDE 272                  // 64 f32 + 16B pad
#define AT_S0   (128 * AQ_STRIDE)      // 34816 (Q region)
#define AT_KV   (64 * AQ_STRIDE)       // 17408
#define AT_STAGE (2 * AT_KV)           // 34816
#define AT_EX   (AT_S0 + 2 * AT_STAGE) // 104448: tm/l exchange (16 slots x 128B)
#define AT_SMEM (AT_EX + 2048)         // 106496
#define AT_NT (S_ / 64)                // 32 k-tiles
#define OX_ROW  264                    // O-exchange row stride bytes (66 f32)

__global__ __launch_bounds__(256, 2) void attn_tc(void)
{
    extern __shared__ char sm[];
    const uint32_t sbase = smem_u32(sm);
    const int tid = threadIdx.x, wid = tid >> 5, lane = tid & 31;
    const int wq = wid & 3, kh = wid >> 2;          // 4 q-warps x 2 key-halves
    const int bh  = blockIdx.y, b = bh >> 4;
    const int qBase = blockIdx.x * 128;
    const size_t ho = (size_t)bh * S_ * D_HEAD;

    const int lr   = lane & 7;
    const int ls8  = ((lane >> 3) & 1) << 3;
    const int lc16 = ((lane >> 4) & 1) << 4;
    const int r0   = lane >> 2, c2 = (lane & 3) << 1;
    const int cg   = lane & 3, gb = lane & 28;

    // ---- Q load: 128 rows x 64 f32 ----
    #pragma unroll
    for (int j = 0; j < 8; j++) {
        int c = j * 256 + tid;
        int r = c >> 4, cc = c & 15;
        uint32_t dst = sbase + r * AQ_STRIDE + cc * 16;
        CP16(dst, g_qt + ho + (size_t)(qBase + r) * D_HEAD + cc * 4);
    }
    CP_COMMIT();

    auto load_stage = [&](int kt, int s) {
        const int k0 = kt * 64;
        const uint32_t stb = sbase + AT_S0 + s * AT_STAGE;
        #pragma unroll
        for (int j = 0; j < 8; j++) {
            int c = j * 256 + tid;
            int t = c >> 10, r = (c >> 4) & 63, cc = c & 15;
            uint32_t dst = stb + t * AT_KV + r * AQ_STRIDE + cc * 16;
            const float* src = t ? (g_vt + ho + (size_t)r * S_ + k0 + cc * 4)
                                 : (g_kt + ho + (size_t)(k0 + r) * D_HEAD + cc * 4);
            CP16(dst, src);
        }
        CP_COMMIT();
    };

    load_stage(0, 0);
    CP_WAIT0();
    __syncthreads();
    load_stage(1, 1);

    const uint32_t rowQ = (wq * 32 + lr + ls8) * AQ_STRIDE;
    const uint32_t rowK = (kh * 32 + lr + ls8) * AQ_STRIDE;
    const uint32_t rowV = (lr + ls8) * AQ_STRIDE;

    float O[2][8][4];
    #pragma unroll
    for (int mt = 0; mt < 2; mt++)
        #pragma unroll
        for (int nt = 0; nt < 8; nt++)
            #pragma unroll
            for (int e = 0; e < 4; e++) O[mt][nt][e] = 0.f;
    float mr[4], lrs[4];
    #pragma unroll
    for (int i = 0; i < 4; i++) { mr[i] = -INFINITY; lrs[i] = 0.f; }

    // mask word base: row(i) = qBase + wq*32 + (i>>1)*16 + (i&1)*8 + r0
    const int mrowBase = (b * S_ + qBase + wq * 32 + r0) * (S_ / 32);

    for (int kt = 0; kt < AT_NT; kt++) {
        const uint32_t stb = sbase + AT_S0 + (kt & 1) * AT_STAGE;

        uint32_t mw[4];
        #pragma unroll
        for (int i = 0; i < 4; i++)
            mw[i] = g_mbits[mrowBase + (i >> 1) * (16 * (S_ / 32)) + (i & 1) * (8 * (S_ / 32))
                            + kt * 2 + kh];

        // ---- scores: m32 x n32 (this warp's key half) ----
        float sc[2][4][4];
        #pragma unroll
        for (int mt = 0; mt < 2; mt++)
            #pragma unroll
            for (int nt = 0; nt < 4; nt++)
                #pragma unroll
                for (int e = 0; e < 4; e++) sc[mt][nt][e] = 0.f;

        #pragma unroll
        for (int kk = 0; kk < 8; kk++) {
            uint32_t qa[2][4], kb2[2][4];
            const uint32_t colOff = kk * 32 + lc16;
            LDSM4(qa[0], sbase + rowQ + colOff);
            LDSM4(qa[1], sbase + rowQ + 16 * AQ_STRIDE + colOff);
            LDSM4(kb2[0], stb + rowK + colOff);
            LDSM4(kb2[1], stb + rowK + 16 * AQ_STRIDE + colOff);
            #pragma unroll
            for (int mt = 0; mt < 2; mt++)
                #pragma unroll
                for (int np = 0; np < 2; np++) {
                    MMA1688(sc[mt][np * 2 + 0], qa[mt], kb2[np][0], kb2[np][2]);
                    MMA1688(sc[mt][np * 2 + 1], qa[mt], kb2[np][1], kb2[np][3]);
                }
        }

        // ---- mask (this half's 32 keys live in one word per row) ----
        #pragma unroll
        for (int mt = 0; mt < 2; mt++)
            #pragma unroll
            for (int nt = 0; nt < 4; nt++)
                #pragma unroll
                for (int e = 0; e < 4; e++) {
                    int keyl = nt * 8 + c2 + (e & 1);
                    if ((mw[mt * 2 + (e >> 1)] >> keyl) & 1u) sc[mt][nt][e] = -INFINITY;
                }

        // ---- local row max + quad reduce ----
        float tm[4];
        #pragma unroll
        for (int i = 0; i < 4; i++) tm[i] = -INFINITY;
        #pragma unroll
        for (int mt = 0; mt < 2; mt++)
            #pragma unroll
            for (int nt = 0; nt < 4; nt++) {
                tm[mt * 2 + 0] = fmaxf(tm[mt * 2 + 0], fmaxf(sc[mt][nt][0], sc[mt][nt][1]));
                tm[mt * 2 + 1] = fmaxf(tm[mt * 2 + 1], fmaxf(sc[mt][nt][2], sc[mt][nt][3]));
            }
        #pragma unroll
        for (int i = 0; i < 4; i++) {
            tm[i] = fmaxf(tm[i], __shfl_xor_sync(0xffffffffu, tm[i], 1));
            tm[i] = fmaxf(tm[i], __shfl_xor_sync(0xffffffffu, tm[i], 2));
        }

        // ---- cross-half max exchange ----
        {
            uint32_t exw = AT_EX + (((kt & 1) * 8) + kh * 4 + wq) * 128;
            if ((lane & 3) == 0) {
                #pragma unroll
                for (int i = 0; i < 4; i++)
                    *(float*)(sm + exw + (i * 8 + r0) * 4) = tm[i];
            }
            __syncthreads();
            uint32_t exr = AT_EX + (((kt & 1) * 8) + (kh ^ 1) * 4 + wq) * 128;
            #pragma unroll
            for (int i = 0; i < 4; i++)
                tm[i] = fmaxf(tm[i], *(const float*)(sm + exr + (i * 8 + r0) * 4));
        }

        // ---- online softmax (shared max, per-warp partial l/O) ----
        float corr[4], bb[4];
        #pragma unroll
        for (int i = 0; i < 4; i++) {
            float nm = fmaxf(mr[i], tm[i]);
            corr[i] = (mr[i] == -INFINITY) ? 1.f : ex2(mr[i] - nm);
            bb[i]   = (nm == -INFINITY) ? 0.f : nm;
            mr[i]   = nm;
        }
        float ps[4] = {0.f, 0.f, 0.f, 0.f};
        #pragma unroll
        for (int mt = 0; mt < 2; mt++)
            #pragma unroll
            for (int nt = 0; nt < 4; nt++) {
                float p0 = ex2(sc[mt][nt][0] - bb[mt * 2]);
                float p1 = ex2(sc[mt][nt][1] - bb[mt * 2]);
                float p2 = ex2(sc[mt][nt][2] - bb[mt * 2 + 1]);
                float p3 = ex2(sc[mt][nt][3] - bb[mt * 2 + 1]);
                sc[mt][nt][0] = p0; sc[mt][nt][1] = p1;
                sc[mt][nt][2] = p2; sc[mt][nt][3] = p3;
                ps[mt * 2] += p0 + p1; ps[mt * 2 + 1] += p2 + p3;
            }
        #pragma unroll
        for (int i = 0; i < 4; i++) lrs[i] = lrs[i] * corr[i] + ps[i];
        #pragma unroll
        for (int mt = 0; mt < 2; mt++)
            #pragma unroll
            for (int nt = 0; nt < 8; nt++) {
                O[mt][nt][0] *= corr[mt * 2];     O[mt][nt][1] *= corr[mt * 2];
                O[mt][nt][2] *= corr[mt * 2 + 1]; O[mt][nt][3] *= corr[mt * 2 + 1];
            }

        // ---- PV over this half's 4 k8 chunks ----
        const int src1 = gb | (cg >> 1);
        const int src2 = src1 + 2;
        const bool odd = (cg & 1) != 0;
        #pragma unroll
        for (int kkl = 0; kkl < 4; kkl++) {
            uint32_t pa[2][4];
            #pragma unroll
            for (int mt = 0; mt < 2; mt++) {
                float v0 = __shfl_sync(0xffffffffu, sc[mt][kkl][0], src1);
                float v1 = __shfl_sync(0xffffffffu, sc[mt][kkl][1], src1);
                float v2 = __shfl_sync(0xffffffffu, sc[mt][kkl][2], src1);
                float v3 = __shfl_sync(0xffffffffu, sc[mt][kkl][3], src1);
                float w0 = __shfl_sync(0xffffffffu, sc[mt][kkl][0], src2);
                float w1 = __shfl_sync(0xffffffffu, sc[mt][kkl][1], src2);
                float w2 = __shfl_sync(0xffffffffu, sc[mt][kkl][2], src2);
                float w3 = __shfl_sync(0xffffffffu, sc[mt][kkl][3], src2);
                pa[mt][0] = tf32r(odd ? v1 : v0);
                pa[mt][1] = tf32r(odd ? v3 : v2);
                pa[mt][2] = tf32r(odd ? w1 : w0);
                pa[mt][3] = tf32r(odd ? w3 : w2);
            }
            const uint32_t colV = (kh * 4 + kkl) * 32 + lc16;
            #pragma unroll
            for (int np = 0; np < 4; np++) {
                uint32_t vb[4];
                LDSM4(vb, stb + AT_KV + rowV + np * (16 * AQ_STRIDE) + colV);
                MMA1688(O[0][np * 2 + 0], pa[0], vb[0], vb[2]);
                MMA1688(O[0][np * 2 + 1], pa[0], vb[1], vb[3]);
                MMA1688(O[1][np * 2 + 0], pa[1], vb[0], vb[2]);
                MMA1688(O[1][np * 2 + 1], pa[1], vb[1], vb[3]);
            }
        }

        // ---- stage transition ----
        if (kt + 1 < AT_NT) {
            CP_WAIT0();
            __syncthreads();
            if (kt + 2 < AT_NT) load_stage(kt + 2, kt & 1);
        }
    }

    // ---- combine halves: quad-reduce l, exchange O + l via smem ----
    #pragma unroll
    for (int i = 0; i < 4; i++) {
        lrs[i] += __shfl_xor_sync(0xffffffffu, lrs[i], 1);
        lrs[i] += __shfl_xor_sync(0xffffffffu, lrs[i], 2);
    }
    __syncthreads();    // all warps done with stage smem + exbuf

    if (kh == 1) {
        #pragma unroll
        for (int mt = 0; mt < 2; mt++)
            #pragma unroll
            for (int nt = 0; nt < 8; nt++) {
                int rl = mt * 16 + r0, d = nt * 8 + c2;
                *(float2*)(sm + AT_S0 + wq * 8448 + rl * OX_ROW + d * 4) =
                    make_float2(O[mt][nt][0], O[mt][nt][1]);
                *(float2*)(sm + AT_S0 + wq * 8448 + (rl + 8) * OX_ROW + d * 4) =
                    make_float2(O[mt][nt][2], O[mt][nt][3]);
            }
        if ((lane & 3) == 0) {
            #pragma unroll
            for (int i = 0; i < 4; i++)
                *(float*)(sm + AT_EX + (4 + wq) * 128 + (i * 8 + r0) * 4) = lrs[i];
        }
    }
    __syncthreads();

    if (kh == 0) {
        float inv[4];
        #pragma unroll
        for (int i = 0; i < 4; i++) {
            float L = lrs[i] + *(const float*)(sm + AT_EX + (4 + wq) * 128 + (i * 8 + r0) * 4);
            inv[i] = (L > 0.f) ? 1.f / L : 0.f;
        }
        #pragma unroll
        for (int mt = 0; mt < 2; mt++)
            #pragma unroll
            for (int nt = 0; nt < 8; nt++) {
                int rl = mt * 16 + r0, d = nt * 8 + c2;
                float2 q0 = *(const float2*)(sm + AT_S0 + wq * 8448 + rl * OX_ROW + d * 4);
                float2 q1 = *(const float2*)(sm + AT_S0 + wq * 8448 + (rl + 8) * OX_ROW + d * 4);
                int grow = qBase + wq * 32 + rl;
                *(float2*)&g_ta[ho + (size_t)grow * D_HEAD + d] =
                    make_float2(tf32f((O[mt][nt][0] + q0.x) * inv[mt * 2]),
                                tf32f((O[mt][nt][1] + q0.y) * inv[mt * 2]));
                *(float2*)&g_ta[ho + (size_t)(grow + 8) * D_HEAD + d] =
                    make_float2(tf32f((O[mt][nt][2] + q1.x) * inv[mt * 2 + 1]),
                                tf32f((O[mt][nt][3] + q1.y) * inv[mt * 2 + 1]));
            }
    }
}

// ---------------------------------------------------------------------------
extern "C" void kernel_launch(void* const* d_in, const int* in_sizes, int n_in,
                              void* d_out, int out_size)
{
    const float* q    = (const float*)d_in[0];
    const float* k    = (const float*)d_in[1];
    const float* v    = (const float*)d_in[2];
    const int*   mask = (const int*)d_in[3];
    const float* w_q  = (const float*)d_in[4];
    const float* w_k  = (const float*)d_in[5];
    const float* w_v  = (const float*)d_in[6];
    const float* w_o  = (const float*)d_in[7];
    float* out = (float*)d_out;

    cudaFuncSetAttribute(gemm_qkv, cudaFuncAttributeMaxDynamicSharedMemorySize, GSMEM);
    cudaFuncSetAttribute(gemm_o,   cudaFuncAttributeMaxDynamicSharedMemorySize, GSMEM);
    cudaFuncSetAttribute(attn_tc,  cudaFuncAttributeMaxDynamicSharedMemorySize, AT_SMEM);

    const int nA4 = AELEM / 4;

    prep_all<<<dim3(nA4 / 256, 8), 256>>>(q, k, v, w_q, w_k, w_v, w_o, mask);

    gemm_qkv<<<dim3(D_MODEL / 128, M_ROWS / 128, 3), 256, GSMEM>>>();

    vtrans<<<dim3(S_ / 32, D_HEAD / 32, B_ * NHEAD), dim3(32, 8)>>>();

    attn_tc<<<dim3(S_ / 128, B_ * NHEAD), 256, AT_SMEM>>>();

    gemm_o<<<dim3(D_MODEL / 128, M_ROWS / 128), 256, GSMEM>>>(out);
}

// round 17
// speedup vs baseline: 1.0598x; 1.0598x over previous
#include <cuda_runtime.h>
#include <math.h>
#include <stdint.h>

#define D_MODEL 1024
#define NHEAD   16
#define D_HEAD  64
#define B_      2
#define S_      2048
#define M_ROWS  (B_*S_)              // 4096
#define AELEM   (M_ROWS * D_MODEL)   // 4M
#define WELEM   (D_MODEL * D_MODEL)  // 1M

// ---------------- scratch (allocation-free) ----------------
__device__ float g_ta[3 * AELEM];   // tf32 inputs q,k,v; seg0 reused for attn output
__device__ float g_tw[4 * WELEM];   // tf32 weights wq,wk,wv,wo
__device__ float g_v [AELEM];       // V projection (tf32-rounded fp32)
__device__ float g_qt[AELEM];       // scaled Q (log2e folded), tf32
__device__ float g_kt[AELEM];       // K, tf32
__device__ float g_vt[AELEM];       // V^T per head [bh][64][2048], tf32
__device__ uint32_t g_mbits[B_ * S_ * (S_/32)];

// ---------------- helpers ----------------
__device__ __forceinline__ uint32_t smem_u32(const void* p) {
    uint32_t a;
    asm("{ .reg .u64 t; cvta.to.shared.u64 t, %1; cvt.u32.u64 %0, t; }" : "=r"(a) : "l"(p));
    return a;
}
#define CP16(dst, src) \
    asm volatile("cp.async.cg.shared.global [%0], [%1], 16;" :: "r"(dst), "l"(src))
#define CP_COMMIT() asm volatile("cp.async.commit_group;" ::: "memory")
#define CP_WAIT0()  asm volatile("cp.async.wait_group 0;" ::: "memory")
#define LDSM4(d, a) \
    asm volatile("ldmatrix.sync.aligned.m8n8.x4.shared.b16 {%0,%1,%2,%3}, [%4];" \
        : "=r"((d)[0]), "=r"((d)[1]), "=r"((d)[2]), "=r"((d)[3]) : "r"(a))
#define MMA1688(c, a, b0, b1) \
    asm volatile("mma.sync.aligned.m16n8k8.row.col.f32.tf32.tf32.f32 " \
        "{%0,%1,%2,%3},{%4,%5,%6,%7},{%8,%9},{%0,%1,%2,%3};" \
        : "+f"((c)[0]), "+f"((c)[1]), "+f"((c)[2]), "+f"((c)[3]) \
        : "r"((a)[0]), "r"((a)[1]), "r"((a)[2]), "r"((a)[3]), "r"(b0), "r"(b1))

__device__ __forceinline__ uint32_t tf32r(float x) {
    uint32_t r;
    asm("cvt.rna.tf32.f32 %0, %1;" : "=r"(r) : "f"(x));
    return r;
}
__device__ __forceinline__ float tf32f(float x) { uint32_t r = tf32r(x); return __uint_as_float(r); }
__device__ __forceinline__ float ex2(float x) {
    float y;
    asm("ex2.approx.ftz.f32 %0, %1;" : "=f"(y) : "f"(x));
    return y;
}
#define QSCALE 0.1803368801111243f   /* 0.125 * log2(e) */

// ---------------- prep: tf32 rounding (7 tensors) + mask bitpack, one launch ----------------
__global__ __launch_bounds__(256) void prep_all(
    const float* __restrict__ q, const float* __restrict__ k, const float* __restrict__ v,
    const float* __restrict__ wq, const float* __restrict__ wk,
    const float* __restrict__ wv, const float* __restrict__ wo,
    const int* __restrict__ mask)
{
    const int y = blockIdx.y;
    if (y == 7) {
        int gw = blockIdx.x * 8 + (threadIdx.x >> 5);
        int lane = threadIdx.x & 31;
        #pragma unroll
        for (int i = 0; i < 8; i++) {
            int w = gw * 8 + i;
            int m = mask[((size_t)(w >> 6) << 11) + ((w & 63) << 5) + lane];
            uint32_t word = __ballot_sync(0xffffffffu, m != 0);
            if (lane == 0) g_mbits[w] = word;
        }
        return;
    }
    const float* src; float* dst; int n4;
    if (y < 3) { src = (y==0)?q:(y==1)?k:v; dst = g_ta + (size_t)y * AELEM; n4 = AELEM/4; }
    else { int w = y-3; src = (w==0)?wq:(w==1)?wk:(w==2)?wv:wo; dst = g_tw + (size_t)w*WELEM; n4 = WELEM/4; }
    int i = blockIdx.x * blockDim.x + threadIdx.x;
    if (i >= n4) return;
    float4 x = ((const float4*)src)[i];
    x.x = tf32f(x.x); x.y = tf32f(x.y); x.z = tf32f(x.z); x.w = tf32f(x.w);
    ((float4*)dst)[i] = x;
}

// ---------------- V transpose (pure copy; values pre-rounded): [bh][key][d] -> [bh][d][key] ----------------
__global__ __launch_bounds__(256) void vtrans(void)
{
    __shared__ float t[32][33];
    const int bh = blockIdx.z, kt = blockIdx.x, dt = blockIdx.y;
    const int tx = threadIdx.x, ty = threadIdx.y;
    const size_t ho = (size_t)bh * S_ * D_HEAD;
    #pragma unroll
    for (int i = 0; i < 4; i++) {
        int key = kt * 32 + ty + i * 8;
        t[ty + i * 8][tx] = g_v[ho + (size_t)key * D_HEAD + dt * 32 + tx];
    }
    __syncthreads();
    #pragma unroll
    for (int i = 0; i < 4; i++) {
        int d   = dt * 32 + ty + i * 8;
        int key = kt * 32 + tx;
        g_vt[ho + (size_t)d * S_ + key] = t[tx][ty + i * 8];
    }
}

// ---------------- tf32 GEMM mainloop (2-stage, pipelined frags) ----------------
#define GS_STRIDE 144
#define GS_TILE   (128 * GS_STRIDE)
#define GS_STAGE  (2 * GS_TILE)
#define GSMEM     (2 * GS_STAGE)     // 73728
#define NKB       (D_MODEL / 32)

__device__ __forceinline__ void gemm_body(
    const float* __restrict__ A, const float* __restrict__ W,
    uint32_t sbase, int m0, int n0, int tid, float acc[2][8][4])
{
    const int wid  = tid >> 5, lane = tid & 31;
    const int wm   = wid & 3,  wn   = wid >> 2;
    const int lr   = lane & 7;
    const int ls8  = ((lane >> 3) & 1) << 3;
    const int lc16 = ((lane >> 4) & 1) << 4;

    auto load_stage = [&](int kb, int s) {
        const int k0 = kb * 32;
        const uint32_t stb = sbase + s * GS_STAGE;
        #pragma unroll
        for (int j = 0; j < 8; j++) {
            int c  = j * 256 + tid;
            int t  = c >> 10;
            int r  = (c >> 3) & 127;
            int cc = c & 7;
            uint32_t dst = stb + t * GS_TILE + r * GS_STRIDE + cc * 16;
            const float* src = (t ? W : A) + ((size_t)((t ? n0 : m0) + r) << 10) + k0 + cc * 4;
            CP16(dst, src);
        }
        CP_COMMIT();
    };

    uint32_t af[2][2][4], bf[2][4][4];
    const uint32_t rowAoff = (wm * 32 + lr + ls8) * GS_STRIDE;
    const uint32_t rowBoff = GS_TILE + (wn * 64 + lr + ls8) * GS_STRIDE;

    auto ld_frags = [&](uint32_t stb, int k8, int s) {
        const uint32_t colOff = k8 * 32 + lc16;
        #pragma unroll
        for (int mt = 0; mt < 2; mt++)
            LDSM4(af[s][mt], stb + rowAoff + mt * (16 * GS_STRIDE) + colOff);
        #pragma unroll
        for (int p = 0; p < 4; p++)
            LDSM4(bf[s][p], stb + rowBoff + p * (16 * GS_STRIDE) + colOff);
    };

    #pragma unroll
    for (int mt = 0; mt < 2; mt++)
        #pragma unroll
        for (int nt = 0; nt < 8; nt++)
            #pragma unroll
            for (int e = 0; e < 4; e++) acc[mt][nt][e] = 0.f;

    load_stage(0, 0);
    CP_WAIT0();
    __syncthreads();
    load_stage(1, 1);
    ld_frags(sbase, 0, 0);

    for (int kb = 0; kb < NKB; kb++) {
        const uint32_t stb = sbase + (kb & 1) * GS_STAGE;
        #pragma unroll
        for (int k8 = 0; k8 < 4; k8++) {
            const int s = k8 & 1;
            if (k8 < 3) {
                ld_frags(stb, k8 + 1, s ^ 1);
            } else if (kb + 1 < NKB) {
                CP_WAIT0();
                __syncthreads();
                if (kb + 2 < NKB) load_stage(kb + 2, kb & 1);
                ld_frags(sbase + ((kb + 1) & 1) * GS_STAGE, 0, s ^ 1);
            }
            #pragma unroll
            for (int mt = 0; mt < 2; mt++)
                #pragma unroll
                for (int nt = 0; nt < 8; nt++) {
                    const int p = nt >> 1, ss = nt & 1;
                    MMA1688(acc[mt][nt], af[s][mt], bf[s][p][ss], bf[s][p][ss + 2]);
                }
        }
    }
}

// ---------------- fused Q/K/V projections: grid.z selects tensor ----------------
__global__ __launch_bounds__(256, 2) void gemm_qkv(void)
{
    extern __shared__ char sm[];
    const uint32_t sbase = smem_u32(sm);
    const int tid = threadIdx.x;
    const int z   = blockIdx.z;
    const int m0  = blockIdx.y * 128, n0 = blockIdx.x * 128;

    const float* A = g_ta + (size_t)z * AELEM;
    const float* W = g_tw + (size_t)z * WELEM;

    float acc[2][8][4];
    gemm_body(A, W, sbase, m0, n0, tid, acc);

    const int wid = tid >> 5, lane = tid & 31;
    const int wm = wid & 3, wn = wid >> 2;
    const int erow = lane >> 2, ecol = (lane & 3) << 1;
    const float scale = (z == 0) ? QSCALE : 1.f;
    #pragma unroll
    for (int mt = 0; mt < 2; mt++)
        #pragma unroll
        for (int nt = 0; nt < 8; nt++) {
            int gr = m0 + wm * 32 + mt * 16 + erow;
            int gc = n0 + wn * 64 + nt * 8 + ecol;
            size_t o0 = (size_t)gr * D_MODEL + gc;
            size_t o1 = (size_t)(gr + 8) * D_MODEL + gc;
            if (z == 2) {
                *(float2*)&g_v[o0] = make_float2(tf32f(acc[mt][nt][0]), tf32f(acc[mt][nt][1]));
                *(float2*)&g_v[o1] = make_float2(tf32f(acc[mt][nt][2]), tf32f(acc[mt][nt][3]));
            } else {
                float* T = (z == 0) ? g_qt : g_kt;
                *(float2*)&T[o0] = make_float2(tf32f(acc[mt][nt][0] * scale),
                                               tf32f(acc[mt][nt][1] * scale));
                *(float2*)&T[o1] = make_float2(tf32f(acc[mt][nt][2] * scale),
                                               tf32f(acc[mt][nt][3] * scale));
            }
        }
}

// ---------------- O projection ----------------
__global__ __launch_bounds__(256, 2) void gemm_o(float* __restrict__ C)
{
    extern __shared__ char sm[];
    const uint32_t sbase = smem_u32(sm);
    const int tid = threadIdx.x;
    const int m0  = blockIdx.y * 128, n0 = blockIdx.x * 128;

    float acc[2][8][4];
    gemm_body(g_ta, g_tw + 3 * (size_t)WELEM, sbase, m0, n0, tid, acc);

    const int wid = tid >> 5, lane = tid & 31;
    const int wm = wid & 3, wn = wid >> 2;
    const int erow = lane >> 2, ecol = (lane & 3) << 1;
    #pragma unroll
    for (int mt = 0; mt < 2; mt++)
        #pragma unroll
        for (int nt = 0; nt < 8; nt++) {
            int gr = m0 + wm * 32 + mt * 16 + erow;
            int gc = n0 + wn * 64 + nt * 8 + ecol;
            *(float2*)&C[(size_t)gr * D_MODEL + gc] =
                make_float2(acc[mt][nt][0], acc[mt][nt][1]);
            *(float2*)&C[(size_t)(gr + 8) * D_MODEL + gc] =
                make_float2(acc[mt][nt][2], acc[mt][nt][3]);
        }
}

// ---------------- tf32 flash attention (8 warps x m16) ----------------
#define AQ_STRIDE 272                 // 64 f32 + 16B pad
#define AT_S0   (128 * AQ_STRIDE)     // 34816 (Q region)
#define AT_KV   (64 * AQ_STRIDE)      // 17408
#define AT_STAGE (2 * AT_KV)          // 34816
#define AT_SMEM (AT_S0 + 2 * AT_STAGE)// 104448
#define AT_NT (S_ / 64)               // 32 k-tiles

__global__ __launch_bounds__(256, 2) void attn_tc(void)
{
    extern __shared__ char sm[];
    const uint32_t sbase = smem_u32(sm);
    const int tid = threadIdx.x, wid = tid >> 5, lane = tid & 31;
    const int bh  = blockIdx.y, b = bh >> 4;
    const int qBase = blockIdx.x * 128;
    const size_t ho = (size_t)bh * S_ * D_HEAD;

    const int lr   = lane & 7;
    const int ls8  = ((lane >> 3) & 1) << 3;
    const int lc16 = ((lane >> 4) & 1) << 4;
    const int r0   = lane >> 2, c2 = (lane & 3) << 1;
    const int cg   = lane & 3, gb = lane & 28;

    #pragma unroll
    for (int j = 0; j < 8; j++) {
        int c = j * 256 + tid;
        int r = c >> 4, cc = c & 15;
        uint32_t dst = sbase + r * AQ_STRIDE + cc * 16;
        CP16(dst, g_qt + ho + (size_t)(qBase + r) * D_HEAD + cc * 4);
    }
    CP_COMMIT();

    auto load_stage = [&](int kt, int s) {
        const int k0 = kt * 64;
        const uint32_t stb = sbase + AT_S0 + s * AT_STAGE;
        #pragma unroll
        for (int j = 0; j < 8; j++) {
            int c = j * 256 + tid;
            int t = c >> 10, r = (c >> 4) & 63, cc = c & 15;
            uint32_t dst = stb + t * AT_KV + r * AQ_STRIDE + cc * 16;
            const float* src = t ? (g_vt + ho + (size_t)r * S_ + k0 + cc * 4)
                                 : (g_kt + ho + (size_t)(k0 + r) * D_HEAD + cc * 4);
            CP16(dst, src);
        }
        CP_COMMIT();
    };

    load_stage(0, 0);
    CP_WAIT0();
    __syncthreads();

    uint32_t qf[8][4];
    {
        uint32_t rowA = (wid * 16 + lr + ls8) * AQ_STRIDE;
        #pragma unroll
        for (int kk = 0; kk < 8; kk++)
            LDSM4(qf[kk], sbase + rowA + kk * 32 + lc16);
    }
    load_stage(1, 1);

    const uint32_t rowKV = (lr + ls8) * AQ_STRIDE;

    uint32_t kbf[2][4], vbf[2][4];
    LDSM4(kbf[0], sbase + AT_S0 + rowKV + lc16);

    float O[8][4];
    #pragma unroll
    for (int nt = 0; nt < 8; nt++)
        #pragma unroll
        for (int e = 0; e < 4; e++) O[nt][e] = 0.f;
    float mr0 = -INFINITY, mr1 = -INFINITY, lr0s = 0.f, lr1s = 0.f;

    const int qg0 = qBase + wid * 16 + r0;
    const size_t mrow0 = ((size_t)b * S_ + qg0) * (S_ / 32);
    const size_t mrow1 = mrow0 + 8 * (S_ / 32);

    for (int kt = 0; kt < AT_NT; kt++) {
        const uint32_t stb = sbase + AT_S0 + (kt & 1) * AT_STAGE;

        uint32_t mw00 = g_mbits[mrow0 + kt * 2], mw01 = g_mbits[mrow0 + kt * 2 + 1];
        uint32_t mw10 = g_mbits[mrow1 + kt * 2], mw11 = g_mbits[mrow1 + kt * 2 + 1];

        float sc[8][4];
        #pragma unroll
        for (int nt = 0; nt < 8; nt++)
            #pragma unroll
            for (int e = 0; e < 4; e++) sc[nt][e] = 0.f;

        #pragma unroll
        for (int st = 0; st < 32; st++) {
            const int kk = st >> 2, p = st & 3;
            if (st < 31) {
                const int n = st + 1;
                LDSM4(kbf[n & 1], stb + rowKV + (n & 3) * (16 * AQ_STRIDE) + (n >> 2) * 32 + lc16);
            } else {
                LDSM4(vbf[0], stb + AT_KV + rowKV + lc16);
            }
            uint32_t* kb = kbf[st & 1];
            MMA1688(sc[p * 2 + 0], qf[kk], kb[0], kb[2]);
            MMA1688(sc[p * 2 + 1], qf[kk], kb[1], kb[3]);
        }

        #pragma unroll
        for (int nt = 0; nt < 8; nt++) {
            #pragma unroll
            for (int e = 0; e < 4; e++) {
                int key = nt * 8 + c2 + (e & 1);
                uint32_t word = (e < 2) ? ((key < 32) ? mw00 : mw01)
                                        : ((key < 32) ? mw10 : mw11);
                if ((word >> (key & 31)) & 1u) sc[nt][e] = -INFINITY;
            }
        }

        float tm0 = -INFINITY, tm1 = -INFINITY;
        #pragma unroll
        for (int nt = 0; nt < 8; nt++) {
            tm0 = fmaxf(tm0, fmaxf(sc[nt][0], sc[nt][1]));
            tm1 = fmaxf(tm1, fmaxf(sc[nt][2], sc[nt][3]));
        }
        tm0 = fmaxf(tm0, __shfl_xor_sync(0xffffffffu, tm0, 1));
        tm0 = fmaxf(tm0, __shfl_xor_sync(0xffffffffu, tm0, 2));
        tm1 = fmaxf(tm1, __shfl_xor_sync(0xffffffffu, tm1, 1));
        tm1 = fmaxf(tm1, __shfl_xor_sync(0xffffffffu, tm1, 2));

        float nm0 = fmaxf(mr0, tm0), nm1 = fmaxf(mr1, tm1);
        float corr0 = (mr0 == -INFINITY) ? 1.f : ex2(mr0 - nm0);
        float corr1 = (mr1 == -INFINITY) ? 1.f : ex2(mr1 - nm1);
        float b0 = (nm0 == -INFINITY) ? 0.f : nm0;
        float b1 = (nm1 == -INFINITY) ? 0.f : nm1;

        float ps0 = 0.f, ps1 = 0.f;
        #pragma unroll
        for (int nt = 0; nt < 8; nt++) {
            float p0 = ex2(sc[nt][0] - b0), p1 = ex2(sc[nt][1] - b0);
            float p2 = ex2(sc[nt][2] - b1), p3 = ex2(sc[nt][3] - b1);
            sc[nt][0] = p0; sc[nt][1] = p1; sc[nt][2] = p2; sc[nt][3] = p3;
            ps0 += p0 + p1; ps1 += p2 + p3;
        }
        lr0s = lr0s * corr0 + ps0;
        lr1s = lr1s * corr1 + ps1;
        mr0 = nm0; mr1 = nm1;
        #pragma unroll
        for (int nt = 0; nt < 8; nt++) {
            O[nt][0] *= corr0; O[nt][1] *= corr0;
            O[nt][2] *= corr1; O[nt][3] *= corr1;
        }

        uint32_t pa[4];
        #pragma unroll
        for (int st = 0; st < 32; st++) {
            const int kk = st >> 2, p = st & 3;
            if (st < 31) {
                const int n = st + 1;
                LDSM4(vbf[n & 1], stb + AT_KV + rowKV + (n & 3) * (16 * AQ_STRIDE) + (n >> 2) * 32 + lc16);
            } else if (kt + 1 < AT_NT) {
                CP_WAIT0();
                __syncthreads();
                if (kt + 2 < AT_NT) load_stage(kt + 2, kt & 1);
                LDSM4(kbf[0], sbase + AT_S0 + ((kt + 1) & 1) * AT_STAGE + rowKV + lc16);
            }
            if (p == 0) {
                int src1 = gb | (cg >> 1);
                int src2 = src1 + 2;
                float v0 = __shfl_sync(0xffffffffu, sc[kk][0], src1);
                float v1 = __shfl_sync(0xffffffffu, sc[kk][1], src1);
                float v2 = __shfl_sync(0xffffffffu, sc[kk][2], src1);
                float v3 = __shfl_sync(0xffffffffu, sc[kk][3], src1);
                float w0 = __shfl_sync(0xffffffffu, sc[kk][0], src2);
                float w1 = __shfl_sync(0xffffffffu, sc[kk][1], src2);
                float w2 = __shfl_sync(0xffffffffu, sc[kk][2], src2);
                float w3 = __shfl_sync(0xffffffffu, sc[kk][3], src2);
                bool odd = (cg & 1) != 0;
                pa[0] = tf32r(odd ? v1 : v0);
                pa[1] = tf32r(odd ? v3 : v2);
                pa[2] = tf32r(odd ? w1 : w0);
                pa[3] = tf32r(odd ? w3 : w2);
            }
            uint32_t* vb = vbf[st & 1];
            MMA1688(O[p * 2 + 0], pa, vb[0], vb[2]);
            MMA1688(O[p * 2 + 1], pa, vb[1], vb[3]);
        }
    }

    float L0 = lr0s + __shfl_xor_sync(0xffffffffu, lr0s, 1);
    L0 += __shfl_xor_sync(0xffffffffu, L0, 2);
    float L1 = lr1s + __shfl_xor_sync(0xffffffffu, lr1s, 1);
    L1 += __shfl_xor_sync(0xffffffffu, L1, 2);
    float inv0 = (L0 > 0.f) ? 1.f / L0 : 0.f;
    float inv1 = (L1 > 0.f) ? 1.f / L1 : 0.f;

    #pragma unroll
    for (int nt = 0; nt < 8; nt++) {
        *(float2*)&g_ta[ho + (size_t)qg0 * D_HEAD + nt * 8 + c2] =
            make_float2(tf32f(O[nt][0] * inv0), tf32f(O[nt][1] * inv0));
        *(float2*)&g_ta[ho + (size_t)(qg0 + 8) * D_HEAD + nt * 8 + c2] =
            make_float2(tf32f(O[nt][2] * inv1), tf32f(O[nt][3] * inv1));
    }
}

// ---------------------------------------------------------------------------
extern "C" void kernel_launch(void* const* d_in, const int* in_sizes, int n_in,
                              void* d_out, int out_size)
{
    const float* q    = (const float*)d_in[0];
    const float* k    = (const float*)d_in[1];
    const float* v    = (const float*)d_in[2];
    const int*   mask = (const int*)d_in[3];
    const float* w_q  = (const float*)d_in[4];
    const float* w_k  = (const float*)d_in[5];
    const float* w_v  = (const float*)d_in[6];
    const float* w_o  = (const float*)d_in[7];
    float* out = (float*)d_out;

    cudaFuncSetAttribute(gemm_qkv, cudaFuncAttributeMaxDynamicSharedMemorySize, GSMEM);
    cudaFuncSetAttribute(gemm_o,   cudaFuncAttributeMaxDynamicSharedMemorySize, GSMEM);
    cudaFuncSetAttribute(attn_tc,  cudaFuncAttributeMaxDynamicSharedMemorySize, AT_SMEM);

    const int nA4 = AELEM / 4;

    prep_all<<<dim3(nA4 / 256, 8), 256>>>(q, k, v, w_q, w_k, w_v, w_o, mask);

    gemm_qkv<<<dim3(D_MODEL / 128, M_ROWS / 128, 3), 256, GSMEM>>>();

    vtrans<<<dim3(S_ / 32, D_HEAD / 32, B_ * NHEAD), dim3(32, 8)>>>();

    attn_tc<<<dim3(S_ / 128, B_ * NHEAD), 256, AT_SMEM>>>();

    gemm_o<<<dim3(D_MODEL / 128, M_ROWS / 128), 256, GSMEM>>>(out);
}